// round 1
// baseline (speedup 1.0000x reference)
#include <cuda_runtime.h>
#include <cstdint>

// CTC loss forward (scaled linear-space recursion), specialized for
// B=out_size, T=256, C=128, L=32, S=65. One warp per batch row.
#define T_DIM 256
#define C_DIM 128
#define L_DIM 32
#define S_DIM 65   // 2*L+1
#define WPB   8    // warps (batch rows) per block

__global__ __launch_bounds__(WPB * 32)
void ctc_kernel(const int* __restrict__ y_true,
                const float* __restrict__ y_pred,
                float* __restrict__ out, int B)
{
    __shared__ float sm_e[WPB][C_DIM];        // softmax numerators e[c] per warp
    __shared__ float sm_a[WPB][2][S_DIM + 3]; // double-buffered alpha per warp

    const int w    = threadIdx.x >> 5;
    const int lane = threadIdx.x & 31;
    const int b    = blockIdx.x * WPB + w;
    if (b >= B) return;   // warp-uniform

    // ---- per-lane owned states: s = lane + 32k, k=0..2 -------------------
    const int* lab = y_true + (size_t)b * L_DIM;
    int  ext[3];
    int  skp[3];
#pragma unroll
    for (int k = 0; k < 3; ++k) {
        int s = lane + 32 * k;
        int e = 0, sk = 0;
        if (s < S_DIM && (s & 1)) {       // odd s = real label; even s = blank(0)
            int li = s >> 1;
            e  = lab[li];
            sk = (s >= 3) && (lab[li] != lab[li - 1]);
        }
        ext[k] = e;
        skp[k] = sk;
    }

    const float* row = y_pred + (size_t)b * T_DIM * C_DIM;

    // prefetch t=0 logits: lane owns classes [4*lane, 4*lane+4)
    float4 x = reinterpret_cast<const float4*>(row)[lane];

    float logC = 0.f;
    int   cur  = 0;

    for (int t = 0; t < T_DIM; ++t) {
        // software prefetch of next timestep's logits
        float4 xn = x;
        if (t + 1 < T_DIM)
            xn = reinterpret_cast<const float4*>(row + (size_t)(t + 1) * C_DIM)[lane];

        // ---- softmax numerators over C=128 (warp butterfly reductions) ---
        float m = fmaxf(fmaxf(x.x, x.y), fmaxf(x.z, x.w));
#pragma unroll
        for (int o = 16; o > 0; o >>= 1)
            m = fmaxf(m, __shfl_xor_sync(0xffffffffu, m, o));

        float e0 = __expf(x.x - m);
        float e1 = __expf(x.y - m);
        float e2 = __expf(x.z - m);
        float e3 = __expf(x.w - m);
        reinterpret_cast<float4*>(sm_e[w])[lane] = make_float4(e0, e1, e2, e3);

        float dsum = (e0 + e1) + (e2 + e3);
#pragma unroll
        for (int o = 16; o > 0; o >>= 1)
            dsum += __shfl_xor_sync(0xffffffffu, dsum, o);
        __syncwarp();                      // make sm_e visible cross-lane

        const float inv = 1.0f / dsum;     // p[c] = e[c] * inv

        // ---- alpha recursion: a'[s] = (a[s]+a[s-1]+skip*a[s-2]) * p[ext[s]]
        float nva[3];
        float part = 0.f;
        const float* ao = sm_a[w][cur];
#pragma unroll
        for (int k = 0; k < 3; ++k) {
            int s = lane + 32 * k;
            float v = 0.f;
            if (s < S_DIM) {
                float pe = sm_e[w][ext[k]] * inv;
                if (t == 0) {
                    v = (s < 2) ? pe : 0.f;
                } else {
                    float a = ao[s];
                    if (s > 0)  a += ao[s - 1];
                    if (skp[k]) a += ao[s - 2];
                    v = a * pe;
                }
            }
            nva[k] = v;
            part  += v;
        }
#pragma unroll
        for (int o = 16; o > 0; o >>= 1)
            part += __shfl_xor_sync(0xffffffffu, part, o);

        // rescale to keep alpha ~O(1); accumulate log of the scale
        logC += __logf(part);
        const float r = 1.0f / part;

        float* an = sm_a[w][cur ^ 1];
#pragma unroll
        for (int k = 0; k < 3; ++k) {
            int s = lane + 32 * k;
            if (s < S_DIM) an[s] = nva[k] * r;
        }
        __syncwarp();
        cur ^= 1;
        x = xn;
    }

    if (lane == 0) {
        float aT = sm_a[w][cur][S_DIM - 1] + sm_a[w][cur][S_DIM - 2];
        out[b] = -(logC + __logf(aT));
    }
}

extern "C" void kernel_launch(void* const* d_in, const int* in_sizes, int n_in,
                              void* d_out, int out_size)
{
    const int B = out_size;
    // metadata order: y_true [B,L] int32, y_pred [B,T,C] float32.
    // Defensive: pick the smaller buffer as labels.
    const int*   y_true;
    const float* y_pred;
    if (in_sizes[0] < in_sizes[1]) {
        y_true = (const int*)d_in[0];
        y_pred = (const float*)d_in[1];
    } else {
        y_true = (const int*)d_in[1];
        y_pred = (const float*)d_in[0];
    }
    float* out = (float*)d_out;

    int blocks = (B + WPB - 1) / WPB;
    ctc_kernel<<<blocks, WPB * 32>>>(y_true, y_pred, out, B);
}

// round 2
// speedup vs baseline: 1.8589x; 1.8589x over previous
#include <cuda_runtime.h>
#include <cstdint>

// CTC loss, scaled linear-space forward recursion.
// B=2048, T=256, C=128, L=32, S=65. One warp per batch row.
// Key idea: recursion uses UN-normalized e=exp(logit); softmax denominators
// accumulate on an independent chain (-sum log dsum_t); alpha rescaled only
// every 8 steps. Alpha lives in registers (2 states/lane + 1 uniform state).
#define T_DIM 256
#define C_DIM 128
#define L_DIM 32
#define WPB   2     // warps (batch rows) per block
#define PF    4     // global prefetch depth (timesteps)

__global__ __launch_bounds__(WPB * 32)
void ctc_kernel(const int* __restrict__ y_true,
                const float* __restrict__ y_pred,
                float* __restrict__ out, int B)
{
    __shared__ float sm_e[WPB][2][C_DIM];   // double-buffered exp(logits)

    const int w    = threadIdx.x >> 5;
    const int lane = threadIdx.x & 31;
    const int b    = blockIdx.x * WPB + w;
    if (b >= B) return;                      // warp-uniform

    const unsigned FULL = 0xffffffffu;

    // States owned by this lane: s0 = lane, s1 = lane + 32. s=64 is uniform.
    // Odd s -> label lab[s>>1]; even s -> blank (class 0).
    const int* lab = y_true + (size_t)b * L_DIM;
    int   ext0 = 0, ext1 = 0;
    float sk0 = 0.f, sk1 = 0.f;
    if (lane & 1) {
        int l0 = lane >> 1;
        ext0 = lab[l0];
        if (lane >= 3) sk0 = (lab[l0] != lab[l0 - 1]) ? 1.f : 0.f;
        int l1 = 16 + (lane >> 1);           // (lane+32)>>1
        ext1 = lab[l1];
        sk1 = (lab[l1] != lab[l1 - 1]) ? 1.f : 0.f;   // s>=33 -> always >=3
    }

    const float4* rowp =
        reinterpret_cast<const float4*>(y_pred + (size_t)b * T_DIM * C_DIM);
    // lane's float4 slot at timestep t: rowp[t*32 + lane]

    float4 ring[PF];
#pragma unroll
    for (int i = 0; i < PF; ++i) ring[i] = rowp[i * 32 + lane];

    // Virtual init alpha_{-1} = delta at s=0 makes t=0 a normal step.
    float a0  = (lane == 0) ? 1.f : 0.f;
    float a1  = 0.f;
    float a2  = 0.f;                          // s=64, identical on all lanes
    float acc = 0.f;                          // sum(log part) - sum(log dsum)

    for (int tb = 0; tb < T_DIM; tb += 8) {
#pragma unroll
        for (int u = 0; u < 8; ++u) {
            const int t  = tb + u;
            const int ri = u & (PF - 1);
            const int bi = t & 1;

            float4 x = ring[ri];
            if (t + PF < T_DIM) ring[ri] = rowp[(t + PF) * 32 + lane];

            // e = exp(x) (no max-subtraction: cancels exactly in linear recursion)
            float e0 = __expf(x.x), e1 = __expf(x.y);
            float e2 = __expf(x.z), e3 = __expf(x.w);
            reinterpret_cast<float4*>(sm_e[w][bi])[lane] =
                make_float4(e0, e1, e2, e3);
            float d = (e0 + e1) + (e2 + e3);
            __syncwarp();

            // gathers (feed alpha chain)
            float eg0 = sm_e[w][bi][ext0];
            float eg1 = sm_e[w][bi][ext1];
            float eb  = sm_e[w][bi][0];

            // dsum reduce + log: independent chain, overlaps across iterations
#pragma unroll
            for (int o = 16; o > 0; o >>= 1)
                d += __shfl_xor_sync(FULL, d, o);
            acc -= __logf(d);

            // alpha neighbors (read before overwrite)
            float u0_1  = __shfl_up_sync(FULL, a0, 1);
            float u0_2  = __shfl_up_sync(FULL, a0, 2);
            float u1_1  = __shfl_up_sync(FULL, a1, 1);
            float u1_2  = __shfl_up_sync(FULL, a1, 2);
            float a0_31 = __shfl_sync(FULL, a0, 31);
            float a0_30 = __shfl_sync(FULL, a0, 30);
            float a1_31 = __shfl_sync(FULL, a1, 31);

            float am1_0 = (lane == 0) ? 0.f : u0_1;
            float am2_0 = (lane <  2) ? 0.f : u0_2;
            float am1_1 = (lane == 0) ? a0_31 : u1_1;
            float am2_1 = (lane == 0) ? a0_30 : ((lane == 1) ? a0_31 : u1_2);

            float n0 = (a0 + am1_0 + sk0 * am2_0) * eg0;
            float n1 = (a1 + am1_1 + sk1 * am2_1) * eg1;
            float n2 = (a2 + a1_31) * eb;       // s=64: blank, no skip; uniform
            a0 = n0; a1 = n1; a2 = n2;
        }

        // rescale every 8 steps: keeps alpha in fp32 range
        float psum = a0 + a1 + ((lane == 0) ? a2 : 0.f);
#pragma unroll
        for (int o = 16; o > 0; o >>= 1)
            psum += __shfl_xor_sync(FULL, psum, o);
        float r = 1.f / psum;
        a0 *= r; a1 *= r; a2 *= r;
        acc += __logf(psum);
    }

    // loss = -( log(alpha_T[S-1] + alpha_T[S-2]) + acc )
    float a1_31 = __shfl_sync(FULL, a1, 31);
    if (lane == 0)
        out[b] = -(__logf(a1_31 + a2) + acc);
}

extern "C" void kernel_launch(void* const* d_in, const int* in_sizes, int n_in,
                              void* d_out, int out_size)
{
    const int B = out_size;
    const int*   y_true;
    const float* y_pred;
    if (in_sizes[0] < in_sizes[1]) {       // labels buffer is the smaller one
        y_true = (const int*)d_in[0];
        y_pred = (const float*)d_in[1];
    } else {
        y_true = (const int*)d_in[1];
        y_pred = (const float*)d_in[0];
    }
    float* outp = (float*)d_out;

    int blocks = (B + WPB - 1) / WPB;
    ctc_kernel<<<blocks, WPB * 32>>>(y_true, y_pred, outp, B);
}